// round 11
// baseline (speedup 1.0000x reference)
#include <cuda_runtime.h>
#include <math.h>
#include <stdint.h>

#define PRIMEY 2654435761u

struct Res8 { float rx[8]; float ry[8]; };

__constant__ float4 c_w1[128];  // w1[16][32]
__constant__ float4 c_b1[8];    // b1[32]
__constant__ float4 c_w2[192];  // w2[32][24]
__constant__ float4 c_b2[6];    // b2[24]

__device__ __forceinline__ float4 exp4(float4 v) {
    return make_float4(__expf(v.x), __expf(v.y), __expf(v.z), __expf(v.w));
}
__device__ __forceinline__ float sigm1(float v) { return 1.0f / (1.0f + __expf(-v)); }
__device__ __forceinline__ float4 sig4(float4 v) {
    return make_float4(sigm1(v.x), sigm1(v.y), sigm1(v.z), sigm1(v.w));
}

// Per-level in-flight gather state
struct Lv {
    float4 q0, q1;    // aligned pairs containing corner (x0,y0) / (x0,y1)
    float2 g10, g11;  // extra gathers, valid only when xodd
    float  wx, wy;
    int    hi0, hi1, xodd;
};

__device__ __forceinline__ void issue_level(
    int l, float2 xp, const float2* __restrict__ tb, const Res8& rr, Lv& v)
{
    float px = xp.x * rr.rx[l];
    float py = xp.y * rr.ry[l];
    float fx = floorf(px), fy = floorf(py);
    v.wx = px - fx; v.wy = py - fy;
    unsigned xi = (unsigned)fx, yi = (unsigned)fy;
    unsigned hy0 = yi * PRIMEY;
    unsigned hy1 = hy0 + PRIMEY;          // (yi+1)*PRIMEY mod 2^32
    const float2* tl  = tb + l * 16384;
    const float4* tl4 = (const float4*)tl;
    unsigned i00 = (xi ^ hy0) & 16383u;
    unsigned i01 = (xi ^ hy1) & 16383u;
    v.hi0  = (int)(i00 & 1u);
    v.hi1  = (int)(i01 & 1u);
    v.xodd = (int)(xi & 1u);
    v.q0 = __ldg(tl4 + (i00 >> 1));
    v.q1 = __ldg(tl4 + (i01 >> 1));
    if (v.xodd) {
        v.g10 = __ldg(tl + (((xi + 1u) ^ hy0) & 16383u));
        v.g11 = __ldg(tl + (((xi + 1u) ^ hy1) & 16383u));
    }
}

__device__ __forceinline__ void consume_level(int l, const Lv& v, float* H)
{
    float2 f00 = v.hi0 ? make_float2(v.q0.z, v.q0.w) : make_float2(v.q0.x, v.q0.y);
    float2 o0  = v.hi0 ? make_float2(v.q0.x, v.q0.y) : make_float2(v.q0.z, v.q0.w);
    float2 f10 = v.xodd ? v.g10 : o0;
    float2 f01 = v.hi1 ? make_float2(v.q1.z, v.q1.w) : make_float2(v.q1.x, v.q1.y);
    float2 o1  = v.hi1 ? make_float2(v.q1.x, v.q1.y) : make_float2(v.q1.z, v.q1.w);
    float2 f11 = v.xodd ? v.g11 : o1;

    float wx = v.wx, wy = v.wy;
    float w00 = (1.f - wx) * (1.f - wy);
    float w10 = wx * (1.f - wy);
    float w01 = (1.f - wx) * wy;
    float w11 = wx * wy;
    H[2 * l]     = f00.x * w00 + f10.x * w10 + f01.x * w01 + f11.x * w11;
    H[2 * l + 1] = f00.y * w00 + f10.y * w10 + f01.y * w01 + f11.y * w11;
}

// Shared MLP + epilogue + store for one point
__device__ __forceinline__ void store_point(
    const float* H, const float4* h1, float4* out4, size_t n2, int p)
{
    // Layer 2: raw[24] = h1[32] @ w2[32,24] + b2 (weights loaded by caller? no — here)
    // (kept inside pair kernel for weight sharing; this fn only does epilogue+store)
    // -- unused --
}

__global__ void __launch_bounds__(128, 4) pg_pair_kernel(
    const float2* __restrict__ xs,
    const int*    __restrict__ hashidxs,
    const float*  __restrict__ table,
    float4*       __restrict__ out4,
    int n, Res8 rr)
{
    int pA = blockIdx.x * 256 + threadIdx.x;
    int pB = pA + 128;

    float2 xA = __ldg(xs + pA);
    float2 xB = __ldg(xs + pB);
    const float2* tbA = (const float2*)table + (size_t)__ldg(hashidxs + pA) * (8u * 16384u);
    const float2* tbB = (const float2*)table + (size_t)__ldg(hashidxs + pB) * (8u * 16384u);

    float HA[16], HB[16];
    Lv a0, a1, b0, b1;
    issue_level(0, xA, tbA, rr, a0);
    issue_level(0, xB, tbB, rr, b0);
#pragma unroll
    for (int l = 0; l < 8; l++) {
        if (l & 1) {
            if (l < 7) { issue_level(l + 1, xA, tbA, rr, a0); issue_level(l + 1, xB, tbB, rr, b0); }
            consume_level(l, a1, HA);
            consume_level(l, b1, HB);
        } else {
            if (l < 7) { issue_level(l + 1, xA, tbA, rr, a1); issue_level(l + 1, xB, tbB, rr, b1); }
            consume_level(l, a0, HA);
            consume_level(l, b0, HB);
        }
    }

    // Layer 1 for both points; each weight float4 loaded once, used twice
    float4 h1A[8], h1B[8];
#pragma unroll
    for (int j = 0; j < 8; j++) { float4 b = c_b1[j]; h1A[j] = b; h1B[j] = b; }
#pragma unroll
    for (int i = 0; i < 16; i++) {
        float ha = HA[i], hb = HB[i];
#pragma unroll
        for (int j = 0; j < 8; j++) {
            float4 w = c_w1[i * 8 + j];
            h1A[j].x = fmaf(ha, w.x, h1A[j].x);
            h1A[j].y = fmaf(ha, w.y, h1A[j].y);
            h1A[j].z = fmaf(ha, w.z, h1A[j].z);
            h1A[j].w = fmaf(ha, w.w, h1A[j].w);
            h1B[j].x = fmaf(hb, w.x, h1B[j].x);
            h1B[j].y = fmaf(hb, w.y, h1B[j].y);
            h1B[j].z = fmaf(hb, w.z, h1B[j].z);
            h1B[j].w = fmaf(hb, w.w, h1B[j].w);
        }
    }
#pragma unroll
    for (int j = 0; j < 8; j++) {
        h1A[j].x = __expf(h1A[j].x * h1A[j].x * -50.f);
        h1A[j].y = __expf(h1A[j].y * h1A[j].y * -50.f);
        h1A[j].z = __expf(h1A[j].z * h1A[j].z * -50.f);
        h1A[j].w = __expf(h1A[j].w * h1A[j].w * -50.f);
        h1B[j].x = __expf(h1B[j].x * h1B[j].x * -50.f);
        h1B[j].y = __expf(h1B[j].y * h1B[j].y * -50.f);
        h1B[j].z = __expf(h1B[j].z * h1B[j].z * -50.f);
        h1B[j].w = __expf(h1B[j].w * h1B[j].w * -50.f);
    }

    // Layer 2 for both points, shared weight loads
    float4 rawA[6], rawB[6];
#pragma unroll
    for (int o = 0; o < 6; o++) { float4 b = c_b2[o]; rawA[o] = b; rawB[o] = b; }
#pragma unroll
    for (int j = 0; j < 8; j++) {
        float hvA[4] = {h1A[j].x, h1A[j].y, h1A[j].z, h1A[j].w};
        float hvB[4] = {h1B[j].x, h1B[j].y, h1B[j].z, h1B[j].w};
#pragma unroll
        for (int c = 0; c < 4; c++) {
            float ha = hvA[c], hb = hvB[c];
            int t = j * 4 + c;
#pragma unroll
            for (int o = 0; o < 6; o++) {
                float4 w = c_w2[t * 6 + o];
                rawA[o].x = fmaf(ha, w.x, rawA[o].x);
                rawA[o].y = fmaf(ha, w.y, rawA[o].y);
                rawA[o].z = fmaf(ha, w.z, rawA[o].z);
                rawA[o].w = fmaf(ha, w.w, rawA[o].w);
                rawB[o].x = fmaf(hb, w.x, rawB[o].x);
                rawB[o].y = fmaf(hb, w.y, rawB[o].y);
                rawB[o].z = fmaf(hb, w.z, rawB[o].z);
                rawB[o].w = fmaf(hb, w.w, rawB[o].w);
            }
        }
    }

    // Epilogue + stores. Output layout (float4 units): mu | inv_sigma | weight | H
    size_t n2 = (size_t)n * 2;
    float4* mup = out4;
    float4* isp = out4 + n2;
    float4* wtp = out4 + 2 * n2;
    float4* Hp  = out4 + 3 * n2;

    {
        size_t p2 = (size_t)pA * 2;
        mup[p2]     = sig4(rawA[2]); mup[p2 + 1] = sig4(rawA[3]);
        isp[p2]     = exp4(rawA[4]); isp[p2 + 1] = exp4(rawA[5]);
        wtp[p2]     = exp4(rawA[0]); wtp[p2 + 1] = exp4(rawA[1]);
        size_t p4 = (size_t)pA * 4;
        Hp[p4 + 0] = make_float4(HA[0],  HA[1],  HA[2],  HA[3]);
        Hp[p4 + 1] = make_float4(HA[4],  HA[5],  HA[6],  HA[7]);
        Hp[p4 + 2] = make_float4(HA[8],  HA[9],  HA[10], HA[11]);
        Hp[p4 + 3] = make_float4(HA[12], HA[13], HA[14], HA[15]);
    }
    {
        size_t p2 = (size_t)pB * 2;
        mup[p2]     = sig4(rawB[2]); mup[p2 + 1] = sig4(rawB[3]);
        isp[p2]     = exp4(rawB[4]); isp[p2 + 1] = exp4(rawB[5]);
        wtp[p2]     = exp4(rawB[0]); wtp[p2 + 1] = exp4(rawB[1]);
        size_t p4 = (size_t)pB * 4;
        Hp[p4 + 0] = make_float4(HB[0],  HB[1],  HB[2],  HB[3]);
        Hp[p4 + 1] = make_float4(HB[4],  HB[5],  HB[6],  HB[7]);
        Hp[p4 + 2] = make_float4(HB[8],  HB[9],  HB[10], HB[11]);
        Hp[p4 + 3] = make_float4(HB[12], HB[13], HB[14], HB[15]);
    }
}

// Single-point fallback kernel for the tail (n not divisible by 256)
__global__ void __launch_bounds__(256) pg_tail_kernel(
    const float2* __restrict__ xs,
    const int*    __restrict__ hashidxs,
    const float*  __restrict__ table,
    float4*       __restrict__ out4,
    int n, int start, Res8 rr)
{
    int p = start + blockIdx.x * 256 + threadIdx.x;
    if (p >= n) return;

    float2 xp = __ldg(xs + p);
    const float2* tb = (const float2*)table + (size_t)__ldg(hashidxs + p) * (8u * 16384u);

    float H[16];
    Lv va;
#pragma unroll
    for (int l = 0; l < 8; l++) {
        issue_level(l, xp, tb, rr, va);
        consume_level(l, va, H);
    }

    float4 h1[8];
#pragma unroll
    for (int j = 0; j < 8; j++) h1[j] = c_b1[j];
#pragma unroll
    for (int i = 0; i < 16; i++) {
        float hi = H[i];
#pragma unroll
        for (int j = 0; j < 8; j++) {
            float4 w = c_w1[i * 8 + j];
            h1[j].x = fmaf(hi, w.x, h1[j].x);
            h1[j].y = fmaf(hi, w.y, h1[j].y);
            h1[j].z = fmaf(hi, w.z, h1[j].z);
            h1[j].w = fmaf(hi, w.w, h1[j].w);
        }
    }
#pragma unroll
    for (int j = 0; j < 8; j++) {
        h1[j].x = __expf(h1[j].x * h1[j].x * -50.f);
        h1[j].y = __expf(h1[j].y * h1[j].y * -50.f);
        h1[j].z = __expf(h1[j].z * h1[j].z * -50.f);
        h1[j].w = __expf(h1[j].w * h1[j].w * -50.f);
    }

    float4 raw[6];
#pragma unroll
    for (int o = 0; o < 6; o++) raw[o] = c_b2[o];
#pragma unroll
    for (int j = 0; j < 8; j++) {
        float hv4[4] = {h1[j].x, h1[j].y, h1[j].z, h1[j].w};
#pragma unroll
        for (int c = 0; c < 4; c++) {
            float ht = hv4[c];
            int t = j * 4 + c;
#pragma unroll
            for (int o = 0; o < 6; o++) {
                float4 w = c_w2[t * 6 + o];
                raw[o].x = fmaf(ht, w.x, raw[o].x);
                raw[o].y = fmaf(ht, w.y, raw[o].y);
                raw[o].z = fmaf(ht, w.z, raw[o].z);
                raw[o].w = fmaf(ht, w.w, raw[o].w);
            }
        }
    }

    size_t n2 = (size_t)n * 2;
    float4* mup = out4;
    float4* isp = out4 + n2;
    float4* wtp = out4 + 2 * n2;
    float4* Hp  = out4 + 3 * n2;
    size_t p2 = (size_t)p * 2;
    mup[p2]     = sig4(raw[2]); mup[p2 + 1] = sig4(raw[3]);
    isp[p2]     = exp4(raw[4]); isp[p2 + 1] = exp4(raw[5]);
    wtp[p2]     = exp4(raw[0]); wtp[p2 + 1] = exp4(raw[1]);
    size_t p4 = (size_t)p * 4;
    Hp[p4 + 0] = make_float4(H[0],  H[1],  H[2],  H[3]);
    Hp[p4 + 1] = make_float4(H[4],  H[5],  H[6],  H[7]);
    Hp[p4 + 2] = make_float4(H[8],  H[9],  H[10], H[11]);
    Hp[p4 + 3] = make_float4(H[12], H[13], H[14], H[15]);
}

extern "C" void kernel_launch(void* const* d_in, const int* in_sizes, int n_in,
                              void* d_out, int out_size) {
    const float2* x     = (const float2*)d_in[0];
    const int*    hidx  = (const int*)d_in[1];
    // d_in[2] = color (unused by reference outputs)
    const float*  table = (const float*)d_in[3];
    int n = in_sizes[1];

    // Stage MLP weights into constant memory (async D2D copies; graph-capturable)
    cudaMemcpyToSymbolAsync(c_w1, d_in[4], 16 * 32 * sizeof(float), 0, cudaMemcpyDeviceToDevice, 0);
    cudaMemcpyToSymbolAsync(c_b1, d_in[5], 32 * sizeof(float),      0, cudaMemcpyDeviceToDevice, 0);
    cudaMemcpyToSymbolAsync(c_w2, d_in[6], 32 * 24 * sizeof(float), 0, cudaMemcpyDeviceToDevice, 0);
    cudaMemcpyToSymbolAsync(c_b2, d_in[7], 24 * sizeof(float),      0, cudaMemcpyDeviceToDevice, 0);

    // Mirror reference _level_resolutions() in double precision
    Res8 rr;
    double bx = exp((log(1024.0) - log(16.0)) / 7.0);
    double by = exp((log(768.0)  - log(16.0)) / 7.0);
    for (int l = 0; l < 8; l++) {
        rr.rx[l] = (float)floor(16.0 * pow(bx, (double)l));
        rr.ry[l] = (float)floor(16.0 * pow(by, (double)l));
    }

    int pair_blocks = n / 256;               // each block covers 256 points (2/thread)
    if (pair_blocks > 0)
        pg_pair_kernel<<<pair_blocks, 128>>>(x, hidx, table, (float4*)d_out, n, rr);
    int done = pair_blocks * 256;
    int tail = n - done;
    if (tail > 0) {
        int tb = (tail + 255) / 256;
        pg_tail_kernel<<<tb, 256>>>(x, hidx, table, (float4*)d_out, n, done, rr);
    }
}